// round 6
// baseline (speedup 1.0000x reference)
#include <cuda_runtime.h>
#include <cuda_bf16.h>
#include <cstdint>

// Problem constants
#define BB   8
#define NTOK 4096
#define DMODEL 512
#define HH   8
#define DH   64
#define WW   128
#define PP   32
#define DISP 64

// ---------------------------------------------------------------------------
// Scratch (__device__ globals; allocation-free rule)
// ---------------------------------------------------------------------------
__device__ __nv_bfloat16 g_q0[BB*HH*PP*WW*DH];
__device__ __nv_bfloat16 g_q1[BB*HH*PP*WW*DH];
__device__ __nv_bfloat16 g_k0[BB*HH*PP*WW*DH];
__device__ __nv_bfloat16 g_k1[BB*HH*PP*WW*DH];
__device__ __nv_bfloat16 g_v0[BB*HH*PP*WW*DH];
__device__ __nv_bfloat16 g_v1[BB*HH*PP*WW*DH];
__device__ __nv_bfloat16 g_xa0[BB*NTOK*DMODEL];
__device__ __nv_bfloat16 g_xa1[BB*NTOK*DMODEL];
__device__ __nv_bfloat16 g_wq0[3*HH*DH*DMODEL];
__device__ __nv_bfloat16 g_wq1[3*HH*DH*DMODEL];
__device__ __nv_bfloat16 g_wo0[DMODEL*DMODEL];
__device__ __nv_bfloat16 g_wo1[DMODEL*DMODEL];
__device__ __nv_bfloat16 g_ao0[BB*NTOK*DMODEL];
__device__ __nv_bfloat16 g_ao1[BB*NTOK*DMODEL];

__device__ __forceinline__ uint32_t smem_u32(const void* p) {
    uint32_t a;
    asm("{ .reg .u64 t; cvta.to.shared.u64 t, %1; cvt.u32.u64 %0, t; }"
        : "=r"(a) : "l"(p));
    return a;
}
__device__ __forceinline__ void mma16816(float* d, const uint32_t* a,
                                         uint32_t b0, uint32_t b1) {
    asm volatile(
        "mma.sync.aligned.m16n8k16.row.col.f32.bf16.bf16.f32 "
        "{%0,%1,%2,%3}, {%4,%5,%6,%7}, {%8,%9}, {%0,%1,%2,%3};"
        : "+f"(d[0]), "+f"(d[1]), "+f"(d[2]), "+f"(d[3])
        : "r"(a[0]), "r"(a[1]), "r"(a[2]), "r"(a[3]), "r"(b0), "r"(b1));
}
__device__ __forceinline__ void ldsm_x2_trans(uint32_t& r0, uint32_t& r1, uint32_t addr) {
    asm volatile("ldmatrix.sync.aligned.m8n8.x2.trans.shared.b16 {%0,%1}, [%2];"
                 : "=r"(r0), "=r"(r1) : "r"(addr));
}
__device__ __forceinline__ void pack_split(float x, float y, uint32_t& hi, uint32_t& lo) {
    __nv_bfloat16 hx = __float2bfloat16(x), hy = __float2bfloat16(y);
    float rx = x - __bfloat162float(hx), ry = y - __bfloat162float(hy);
    __nv_bfloat162 h; h.x = hx; h.y = hy;
    __nv_bfloat162 l; l.x = __float2bfloat16(rx); l.y = __float2bfloat16(ry);
    hi = *(uint32_t*)&h; lo = *(uint32_t*)&l;
}

// ---------------------------------------------------------------------------
// Prepass: fp32 -> bf16x2 splits
// ---------------------------------------------------------------------------
__global__ __launch_bounds__(256) void conv_x_kernel(const float* __restrict__ X) {
    int idx = blockIdx.x * 256 + threadIdx.x;
    if (idx >= BB * NTOK * DMODEL) return;
    int r = idx >> 9, k = idx & 511;
    int b = r >> 12, n = r & 4095;
    float v = X[(size_t)(b * NTOK + ((n + DISP) & 4095)) * DMODEL + k];
    __nv_bfloat16 h0 = __float2bfloat16(v);
    float rem = v - __bfloat162float(h0);
    g_xa0[idx] = h0;
    g_xa1[idx] = __float2bfloat16(rem);
}

__global__ __launch_bounds__(256) void conv_w_kernel(const float* __restrict__ src,
                                                     int N, int which) {
    int idx = blockIdx.x * 256 + threadIdx.x;
    if (idx >= N * DMODEL) return;
    int n = idx >> 9, k = idx & 511;
    float v = src[(size_t)k * N + n];
    __nv_bfloat16 h0 = __float2bfloat16(v);
    float rem = v - __bfloat162float(h0);
    if (which == 0) { g_wq0[idx] = h0; g_wq1[idx] = __float2bfloat16(rem); }
    else            { g_wo0[idx] = h0; g_wo1[idx] = __float2bfloat16(rem); }
}

// ---------------------------------------------------------------------------
// mma.sync bf16 GEMM, 128x128 tile, K=512 in 16 chunks of 32, bf16x2 3-pass.
// k-chunk 32 halves smem (80KB) -> 2 CTAs/SM (16 warps) for latency hiding.
// mode 0: C = Xr @ Wqkv^T(cols)  -> scatter bf16x2 q/k/v window layout
// mode 1: C = AO @ Wout^T (+bias) -> d_out with roll(+DISP)
// ---------------------------------------------------------------------------
#define KCH   32
#define TSTR  40                      // row stride (elems): conflict-free
#define TILE_E (128*TSTR)             // 5120
#define TILE_BYTES (TILE_E*2)         // 10240
#define GEMM_SMEM (2*4*TILE_BYTES)    // 81920

__global__ __launch_bounds__(256, 2) void gemm128(const float* __restrict__ bias,
                                                  float* __restrict__ Out, int mode) {
    extern __shared__ char smem_raw[];
    __nv_bfloat16* smem = (__nv_bfloat16*)smem_raw;
    const int tid = threadIdx.x;
    const int wid = tid >> 5;
    const int lid = tid & 31;
    const int row0 = blockIdx.y * 128;
    const int col0 = blockIdx.x * 128;
    const int wm = wid & 3, wn = wid >> 2;
    const int g = lid >> 2, cq = lid & 3;

    const __nv_bfloat16* A0 = mode ? g_ao0 : g_xa0;
    const __nv_bfloat16* A1 = mode ? g_ao1 : g_xa1;
    const __nv_bfloat16* B0 = mode ? g_wo0 : g_wq0;
    const __nv_bfloat16* B1 = mode ? g_wo1 : g_wq1;

    // one 32-wide k-chunk: 4 arrays x 128 rows x 32 elems = 2048 x 16B chunks
    auto issue = [&](int ko, int buf) {
        const int kbase = ko * KCH;
        __nv_bfloat16* tb = smem + buf * 4 * TILE_E;
#pragma unroll
        for (int i = 0; i < 8; i++) {
            const int cidx = tid + i * 256;          // 0..2047
            const int which = cidx >> 9;             // 0:A0 1:A1 2:B0 3:B1
            const int r = (cidx >> 2) & 127;
            const int c8 = cidx & 3;
            const __nv_bfloat16* src;
            if (which == 0)      src = A0 + (size_t)(row0 + r) * 512 + kbase + c8 * 8;
            else if (which == 1) src = A1 + (size_t)(row0 + r) * 512 + kbase + c8 * 8;
            else if (which == 2) src = B0 + (size_t)(col0 + r) * 512 + kbase + c8 * 8;
            else                 src = B1 + (size_t)(col0 + r) * 512 + kbase + c8 * 8;
            const uint32_t dst = smem_u32(tb + which * TILE_E + r * TSTR + c8 * 8);
            asm volatile("cp.async.cg.shared.global [%0], [%1], 16;"
                         :: "r"(dst), "l"(src));
        }
        asm volatile("cp.async.commit_group;");
    };

    float acc[2][8][4];
#pragma unroll
    for (int im = 0; im < 2; im++)
#pragma unroll
        for (int in_ = 0; in_ < 8; in_++)
#pragma unroll
            for (int e = 0; e < 4; e++) acc[im][in_][e] = 0.f;

    issue(0, 0);
    for (int ko = 0; ko < 16; ko++) {
        const int buf = ko & 1;
        if (ko + 1 < 16) {
            issue(ko + 1, buf ^ 1);
            asm volatile("cp.async.wait_group 1;");
        } else {
            asm volatile("cp.async.wait_group 0;");
        }
        __syncthreads();

        const __nv_bfloat16* base = smem + buf * 4 * TILE_E;
        const __nv_bfloat16* Ap0 = base;
        const __nv_bfloat16* Ap1 = base + TILE_E;
        const __nv_bfloat16* Bp0 = base + 2 * TILE_E;
        const __nv_bfloat16* Bp1 = base + 3 * TILE_E;

#pragma unroll
        for (int ks = 0; ks < 2; ks++) {
            const int kofs = ks * 16;
            uint32_t a0f[2][4], a1f[2][4];
#pragma unroll
            for (int im = 0; im < 2; im++) {
                const int rb = wm * 32 + im * 16 + g;
                a0f[im][0] = *(const uint32_t*)(Ap0 + rb * TSTR + kofs + cq * 2);
                a0f[im][1] = *(const uint32_t*)(Ap0 + (rb + 8) * TSTR + kofs + cq * 2);
                a0f[im][2] = *(const uint32_t*)(Ap0 + rb * TSTR + kofs + 8 + cq * 2);
                a0f[im][3] = *(const uint32_t*)(Ap0 + (rb + 8) * TSTR + kofs + 8 + cq * 2);
                a1f[im][0] = *(const uint32_t*)(Ap1 + rb * TSTR + kofs + cq * 2);
                a1f[im][1] = *(const uint32_t*)(Ap1 + (rb + 8) * TSTR + kofs + cq * 2);
                a1f[im][2] = *(const uint32_t*)(Ap1 + rb * TSTR + kofs + 8 + cq * 2);
                a1f[im][3] = *(const uint32_t*)(Ap1 + (rb + 8) * TSTR + kofs + 8 + cq * 2);
            }
#pragma unroll
            for (int in_ = 0; in_ < 8; in_++) {
                const int nr = wn * 64 + in_ * 8 + g;
                const uint32_t b00 = *(const uint32_t*)(Bp0 + nr * TSTR + kofs + cq * 2);
                const uint32_t b01 = *(const uint32_t*)(Bp0 + nr * TSTR + kofs + 8 + cq * 2);
                const uint32_t b10 = *(const uint32_t*)(Bp1 + nr * TSTR + kofs + cq * 2);
                const uint32_t b11 = *(const uint32_t*)(Bp1 + nr * TSTR + kofs + 8 + cq * 2);
                mma16816(acc[0][in_], a0f[0], b00, b01);
                mma16816(acc[0][in_], a0f[0], b10, b11);
                mma16816(acc[0][in_], a1f[0], b00, b01);
                mma16816(acc[1][in_], a0f[1], b00, b01);
                mma16816(acc[1][in_], a0f[1], b10, b11);
                mma16816(acc[1][in_], a1f[1], b00, b01);
            }
        }
        __syncthreads();
    }

    // Epilogue
#pragma unroll
    for (int im = 0; im < 2; im++) {
#pragma unroll
        for (int in_ = 0; in_ < 8; in_++) {
            const int C0 = col0 + wn * 64 + in_ * 8 + cq * 2;
#pragma unroll
            for (int half = 0; half < 2; half++) {
                const int R = row0 + wm * 32 + im * 16 + g + half * 8;
                float vx = acc[im][in_][half * 2];
                float vy = acc[im][in_][half * 2 + 1];
                if (mode == 0) {
                    const int b2 = R >> 12, n2 = R & 4095;
                    const int w = n2 >> 5, jw = n2 & 31;
                    const int part = C0 >> 9;
                    const int h = (C0 & 511) >> 6;
                    const int dh = C0 & 63;
                    const size_t idx = (((size_t)((b2 * HH + h) * PP + jw)) * WW + w) * DH + dh;
                    uint32_t hi, lo;
                    pack_split(vx, vy, hi, lo);
                    __nv_bfloat16* d0 = (part == 0 ? g_q0 : part == 1 ? g_k0 : g_v0);
                    __nv_bfloat16* d1 = (part == 0 ? g_q1 : part == 1 ? g_k1 : g_v1);
                    *(uint32_t*)(d0 + idx) = hi;
                    *(uint32_t*)(d1 + idx) = lo;
                } else {
                    const int b2 = R >> 12, n2 = R & 4095;
                    const int dstn = (n2 + DISP) & 4095;
                    float2 v2;
                    v2.x = vx + __ldg(&bias[C0]);
                    v2.y = vy + __ldg(&bias[C0 + 1]);
                    *(float2*)(Out + (size_t)(b2 * NTOK + dstn) * DMODEL + C0) = v2;
                }
            }
        }
    }
}

// ---------------------------------------------------------------------------
// K2: tensor-core window attention (mask-split into two 64-key halves).
// ---------------------------------------------------------------------------
#define ATSTR 72
#define ATILE_E (WW*ATSTR)
#define ATILE_B (ATILE_E*2)
#define ATT_SMEM (1024 + 6*ATILE_B)          // 111616 B

__global__ __launch_bounds__(256) void attn_kernel(const float* __restrict__ pos_emb) {
    extern __shared__ char smem_raw[];
    float* slut = (float*)smem_raw;
    __nv_bfloat16* tiles = (__nv_bfloat16*)(smem_raw + 1024);

    const int bid = blockIdx.x;
    const int tid = threadIdx.x;
    const int wid = tid >> 5;
    const int lid = tid & 31;
    const int g = lid >> 2, cq = lid & 3;

    if (tid < 2 * WW - 1) slut[tid] = pos_emb[tid];

    const size_t woff = (size_t)bid * (WW * DH);
    const __nv_bfloat16* srcs[6] = { g_q0 + woff, g_q1 + woff, g_k0 + woff,
                                     g_k1 + woff, g_v0 + woff, g_v1 + woff };
#pragma unroll
    for (int arr = 0; arr < 6; arr++) {
        const __nv_bfloat16* src = srcs[arr];
        __nv_bfloat16* tb = tiles + arr * ATILE_E;
#pragma unroll
        for (int ii = 0; ii < 4; ii++) {
            const int idx = ii * 256 + tid;
            const int r = idx >> 3, c8 = idx & 7;
            const uint32_t dst = smem_u32(tb + r * ATSTR + c8 * 8);
            asm volatile("cp.async.cg.shared.global [%0], [%1], 16;"
                         :: "r"(dst), "l"(src + r * 64 + c8 * 8));
        }
    }
    asm volatile("cp.async.commit_group;");
    asm volatile("cp.async.wait_group 0;");
    __syncthreads();

    const __nv_bfloat16* sq0 = tiles;
    const __nv_bfloat16* sq1 = tiles + ATILE_E;
    const __nv_bfloat16* sk0 = tiles + 2 * ATILE_E;
    const __nv_bfloat16* sk1 = tiles + 3 * ATILE_E;
    const __nv_bfloat16* sv0 = tiles + 4 * ATILE_E;
    const __nv_bfloat16* sv1 = tiles + 5 * ATILE_E;

    const int half = wid >> 2;
    const int mrow = (wid & 3) * 16;
    const int qrow0 = half * 64 + mrow;
    const int kbase = half * 64;

    float S[8][4];
#pragma unroll
    for (int nt = 0; nt < 8; nt++)
#pragma unroll
        for (int e = 0; e < 4; e++) S[nt][e] = 0.f;

#pragma unroll
    for (int ks = 0; ks < 4; ks++) {
        const int k0 = ks * 16;
        uint32_t aq0[4], aq1[4];
        aq0[0] = *(const uint32_t*)(sq0 + (qrow0 + g) * ATSTR + k0 + cq * 2);
        aq0[1] = *(const uint32_t*)(sq0 + (qrow0 + g + 8) * ATSTR + k0 + cq * 2);
        aq0[2] = *(const uint32_t*)(sq0 + (qrow0 + g) * ATSTR + k0 + 8 + cq * 2);
        aq0[3] = *(const uint32_t*)(sq0 + (qrow0 + g + 8) * ATSTR + k0 + 8 + cq * 2);
        aq1[0] = *(const uint32_t*)(sq1 + (qrow0 + g) * ATSTR + k0 + cq * 2);
        aq1[1] = *(const uint32_t*)(sq1 + (qrow0 + g + 8) * ATSTR + k0 + cq * 2);
        aq1[2] = *(const uint32_t*)(sq1 + (qrow0 + g) * ATSTR + k0 + 8 + cq * 2);
        aq1[3] = *(const uint32_t*)(sq1 + (qrow0 + g + 8) * ATSTR + k0 + 8 + cq * 2);
#pragma unroll
        for (int nt = 0; nt < 8; nt++) {
            const int krow = kbase + nt * 8 + g;
            const uint32_t b00 = *(const uint32_t*)(sk0 + krow * ATSTR + k0 + cq * 2);
            const uint32_t b01 = *(const uint32_t*)(sk0 + krow * ATSTR + k0 + 8 + cq * 2);
            const uint32_t b10 = *(const uint32_t*)(sk1 + krow * ATSTR + k0 + cq * 2);
            const uint32_t b11 = *(const uint32_t*)(sk1 + krow * ATSTR + k0 + 8 + cq * 2);
            mma16816(S[nt], aq0, b00, b01);
            mma16816(S[nt], aq0, b10, b11);
            mma16816(S[nt], aq1, b00, b01);
        }
    }

    const float scale = 0.125f;
    const int il0 = mrow + g;
    const int il1 = il0 + 8;
    float rs0 = 0.f, rs1 = 0.f;
#pragma unroll
    for (int nt = 0; nt < 8; nt++) {
        const int jl = nt * 8 + cq * 2;
        float p0 = __expf(S[nt][0] * scale + slut[jl - il0 + (WW - 1)]);
        float p1 = __expf(S[nt][1] * scale + slut[jl + 1 - il0 + (WW - 1)]);
        float p2 = __expf(S[nt][2] * scale + slut[jl - il1 + (WW - 1)]);
        float p3 = __expf(S[nt][3] * scale + slut[jl + 1 - il1 + (WW - 1)]);
        S[nt][0] = p0; S[nt][1] = p1; S[nt][2] = p2; S[nt][3] = p3;
        rs0 += p0 + p1;
        rs1 += p2 + p3;
    }
    rs0 += __shfl_xor_sync(0xFFFFFFFF, rs0, 1);
    rs0 += __shfl_xor_sync(0xFFFFFFFF, rs0, 2);
    rs1 += __shfl_xor_sync(0xFFFFFFFF, rs1, 1);
    rs1 += __shfl_xor_sync(0xFFFFFFFF, rs1, 2);
    const float inv0 = 1.0f / rs0;
    const float inv1 = 1.0f / rs1;

    uint32_t p0f[4][4], p1f[4][4];
#pragma unroll
    for (int ks = 0; ks < 4; ks++) {
        pack_split(S[2 * ks][0],     S[2 * ks][1],     p0f[ks][0], p1f[ks][0]);
        pack_split(S[2 * ks][2],     S[2 * ks][3],     p0f[ks][1], p1f[ks][1]);
        pack_split(S[2 * ks + 1][0], S[2 * ks + 1][1], p0f[ks][2], p1f[ks][2]);
        pack_split(S[2 * ks + 1][2], S[2 * ks + 1][3], p0f[ks][3], p1f[ks][3]);
    }

    float O[8][4];
#pragma unroll
    for (int nt = 0; nt < 8; nt++)
#pragma unroll
        for (int e = 0; e < 4; e++) O[nt][e] = 0.f;

#pragma unroll
    for (int ks = 0; ks < 4; ks++) {
        const int vrow = kbase + ks * 16 + (lid & 15);
#pragma unroll
        for (int nt = 0; nt < 8; nt++) {
            uint32_t vb00, vb01, vb10, vb11;
            ldsm_x2_trans(vb00, vb01, smem_u32(sv0 + vrow * ATSTR + nt * 8));
            ldsm_x2_trans(vb10, vb11, smem_u32(sv1 + vrow * ATSTR + nt * 8));
            mma16816(O[nt], p0f[ks], vb00, vb01);
            mma16816(O[nt], p0f[ks], vb10, vb11);
            mma16816(O[nt], p1f[ks], vb00, vb01);
        }
    }

    const int b  = bid >> 8;
    const int h  = (bid >> 5) & 7;
    const int jw = bid & 31;
    const int iw0 = half * 64 + il0;
    const int iw1 = half * 64 + il1;
    const size_t row0off = ((size_t)(b * NTOK + jw * WW + iw0)) * DMODEL + h * DH;
    const size_t row1off = ((size_t)(b * NTOK + jw * WW + iw1)) * DMODEL + h * DH;
#pragma unroll
    for (int nt = 0; nt < 8; nt++) {
        const int c = nt * 8 + cq * 2;
        uint32_t hi, lo;
        pack_split(O[nt][0] * inv0, O[nt][1] * inv0, hi, lo);
        *(uint32_t*)(g_ao0 + row0off + c) = hi;
        *(uint32_t*)(g_ao1 + row0off + c) = lo;
        pack_split(O[nt][2] * inv1, O[nt][3] * inv1, hi, lo);
        *(uint32_t*)(g_ao0 + row1off + c) = hi;
        *(uint32_t*)(g_ao1 + row1off + c) = lo;
    }
}

// ---------------------------------------------------------------------------
extern "C" void kernel_launch(void* const* d_in, const int* in_sizes, int n_in,
                              void* d_out, int out_size) {
    const float* x       = (const float*)d_in[0];
    const float* Wqkv    = (const float*)d_in[1];
    const float* pos_emb = (const float*)d_in[2];
    const float* Wout    = (const float*)d_in[3];
    const float* bout    = (const float*)d_in[4];
    float* out = (float*)d_out;

    cudaFuncSetAttribute(gemm128, cudaFuncAttributeMaxDynamicSharedMemorySize, GEMM_SMEM);
    cudaFuncSetAttribute(attn_kernel, cudaFuncAttributeMaxDynamicSharedMemorySize, ATT_SMEM);

    conv_x_kernel<<<(BB * NTOK * DMODEL + 255) / 256, 256>>>(x);
    conv_w_kernel<<<(1536 * 512 + 255) / 256, 256>>>(Wqkv, 1536, 0);
    conv_w_kernel<<<(512 * 512 + 255) / 256, 256>>>(Wout, 512, 1);

    // K1: QKV (M=32768, N=1536)
    gemm128<<<dim3(12, 256), 256, GEMM_SMEM>>>(nullptr, nullptr, 0);
    // K2: attention, one window per block
    attn_kernel<<<2048, 256, ATT_SMEM>>>(pos_emb);
    // K3: output projection (M=32768, N=512) + bias + roll
    gemm128<<<dim3(4, 256), 256, GEMM_SMEM>>>(bout, out, 1);
}

// round 7
// speedup vs baseline: 1.5519x; 1.5519x over previous
#include <cuda_runtime.h>
#include <cuda_bf16.h>
#include <cstdint>

// Problem constants
#define BB   8
#define NTOK 4096
#define DMODEL 512
#define HH   8
#define DH   64
#define WW   128
#define PP   32
#define DISP 64

// ---------------------------------------------------------------------------
// Scratch (__device__ globals; allocation-free rule)
// ---------------------------------------------------------------------------
__device__ __nv_bfloat16 g_q0[BB*HH*PP*WW*DH];
__device__ __nv_bfloat16 g_q1[BB*HH*PP*WW*DH];
__device__ __nv_bfloat16 g_k0[BB*HH*PP*WW*DH];
__device__ __nv_bfloat16 g_k1[BB*HH*PP*WW*DH];
__device__ __nv_bfloat16 g_v0[BB*HH*PP*WW*DH];
__device__ __nv_bfloat16 g_v1[BB*HH*PP*WW*DH];
__device__ __nv_bfloat16 g_xa0[BB*NTOK*DMODEL];
__device__ __nv_bfloat16 g_xa1[BB*NTOK*DMODEL];
__device__ __nv_bfloat16 g_wq0[3*HH*DH*DMODEL];
__device__ __nv_bfloat16 g_wq1[3*HH*DH*DMODEL];
__device__ __nv_bfloat16 g_wo0[DMODEL*DMODEL];
__device__ __nv_bfloat16 g_wo1[DMODEL*DMODEL];
__device__ __nv_bfloat16 g_ao0[BB*NTOK*DMODEL];
__device__ __nv_bfloat16 g_ao1[BB*NTOK*DMODEL];

__device__ __forceinline__ uint32_t smem_u32(const void* p) {
    uint32_t a;
    asm("{ .reg .u64 t; cvta.to.shared.u64 t, %1; cvt.u32.u64 %0, t; }"
        : "=r"(a) : "l"(p));
    return a;
}
__device__ __forceinline__ void mma16816(float* d, const uint32_t* a,
                                         uint32_t b0, uint32_t b1) {
    asm volatile(
        "mma.sync.aligned.m16n8k16.row.col.f32.bf16.bf16.f32 "
        "{%0,%1,%2,%3}, {%4,%5,%6,%7}, {%8,%9}, {%0,%1,%2,%3};"
        : "+f"(d[0]), "+f"(d[1]), "+f"(d[2]), "+f"(d[3])
        : "r"(a[0]), "r"(a[1]), "r"(a[2]), "r"(a[3]), "r"(b0), "r"(b1));
}
__device__ __forceinline__ void ldsm_x2_trans(uint32_t& r0, uint32_t& r1, uint32_t addr) {
    asm volatile("ldmatrix.sync.aligned.m8n8.x2.trans.shared.b16 {%0,%1}, [%2];"
                 : "=r"(r0), "=r"(r1) : "r"(addr));
}
__device__ __forceinline__ void pack_split(float x, float y, uint32_t& hi, uint32_t& lo) {
    __nv_bfloat16 hx = __float2bfloat16(x), hy = __float2bfloat16(y);
    float rx = x - __bfloat162float(hx), ry = y - __bfloat162float(hy);
    __nv_bfloat162 h; h.x = hx; h.y = hy;
    __nv_bfloat162 l; l.x = __float2bfloat16(rx); l.y = __float2bfloat16(ry);
    hi = *(uint32_t*)&h; lo = *(uint32_t*)&l;
}

// ---------------------------------------------------------------------------
// Prepass: fp32 -> bf16x2 splits
// ---------------------------------------------------------------------------
__global__ __launch_bounds__(256) void conv_x_kernel(const float* __restrict__ X) {
    int idx = blockIdx.x * 256 + threadIdx.x;
    if (idx >= BB * NTOK * DMODEL) return;
    int r = idx >> 9, k = idx & 511;
    int b = r >> 12, n = r & 4095;
    float v = X[(size_t)(b * NTOK + ((n + DISP) & 4095)) * DMODEL + k];
    __nv_bfloat16 h0 = __float2bfloat16(v);
    float rem = v - __bfloat162float(h0);
    g_xa0[idx] = h0;
    g_xa1[idx] = __float2bfloat16(rem);
}

__global__ __launch_bounds__(256) void conv_w_kernel(const float* __restrict__ src,
                                                     int N, int which) {
    int idx = blockIdx.x * 256 + threadIdx.x;
    if (idx >= N * DMODEL) return;
    int n = idx >> 9, k = idx & 511;
    float v = src[(size_t)k * N + n];
    __nv_bfloat16 h0 = __float2bfloat16(v);
    float rem = v - __bfloat162float(h0);
    if (which == 0) { g_wq0[idx] = h0; g_wq1[idx] = __float2bfloat16(rem); }
    else            { g_wo0[idx] = h0; g_wo1[idx] = __float2bfloat16(rem); }
}

// ---------------------------------------------------------------------------
// mma.sync bf16 GEMM, block tile 256x128, 8 warps each 64x64 (crossbar-
// efficient: MMA:LDS cyc ratio 1.5 vs 0.75 of the 32x64 warptile).
// K=512 in 8 chunks of 64, 2-stage cp.async, bf16x2 3-pass split.
// mode 0: C = Xr @ Wqkv^T(cols)  -> scatter bf16x2 q/k/v window layout
// mode 1: C = AO @ Wout^T (+bias) -> d_out with roll(+DISP)
// ---------------------------------------------------------------------------
#define KCH   64
#define TSTR  72
#define TILE_A_E (256*TSTR)                 // 18432 elems
#define TILE_B_E (128*TSTR)                 // 9216 elems
#define STAGE_E  (2*TILE_A_E + 2*TILE_B_E)  // 55296 elems
#define GEMM_SMEM (2*STAGE_E*2)             // 221184 B

__global__ __launch_bounds__(256) void gemm256(const float* __restrict__ bias,
                                               float* __restrict__ Out, int mode) {
    extern __shared__ char smem_raw[];
    __nv_bfloat16* smem = (__nv_bfloat16*)smem_raw;
    const int tid = threadIdx.x;
    const int wid = tid >> 5;
    const int lid = tid & 31;
    const int row0 = blockIdx.y * 256;
    const int col0 = blockIdx.x * 128;
    const int wm = wid & 3, wn = wid >> 2;     // 4 x 2 warp grid
    const int g = lid >> 2, cq = lid & 3;

    const __nv_bfloat16* A0 = mode ? g_ao0 : g_xa0;
    const __nv_bfloat16* A1 = mode ? g_ao1 : g_xa1;
    const __nv_bfloat16* B0 = mode ? g_wo0 : g_wq0;
    const __nv_bfloat16* B1 = mode ? g_wo1 : g_wq1;

    // one 64-wide k-chunk: A: 2 arrays x 256 rows x 8 16B-chunks = 4096
    //                      B: 2 arrays x 128 rows x 8          = 2048
    auto issue = [&](int ko, int buf) {
        const int kbase = ko * KCH;
        __nv_bfloat16* st = smem + buf * STAGE_E;
#pragma unroll
        for (int i = 0; i < 24; i++) {
            const int cidx = tid + i * 256;          // 0..6143
            const __nv_bfloat16* src;
            uint32_t dst;
            if (cidx < 4096) {
                const int arr = cidx >> 11;          // A0 / A1
                const int r = (cidx >> 3) & 255;
                const int c8 = cidx & 7;
                src = (arr ? A1 : A0) + (size_t)(row0 + r) * 512 + kbase + c8 * 8;
                dst = smem_u32(st + arr * TILE_A_E + r * TSTR + c8 * 8);
            } else {
                const int rem = cidx - 4096;         // 0..2047
                const int arr = rem >> 10;           // B0 / B1
                const int r = (rem >> 3) & 127;
                const int c8 = rem & 7;
                src = (arr ? B1 : B0) + (size_t)(col0 + r) * 512 + kbase + c8 * 8;
                dst = smem_u32(st + 2 * TILE_A_E + arr * TILE_B_E + r * TSTR + c8 * 8);
            }
            asm volatile("cp.async.cg.shared.global [%0], [%1], 16;"
                         :: "r"(dst), "l"(src));
        }
        asm volatile("cp.async.commit_group;");
    };

    float acc[4][8][4];
#pragma unroll
    for (int im = 0; im < 4; im++)
#pragma unroll
        for (int in_ = 0; in_ < 8; in_++)
#pragma unroll
            for (int e = 0; e < 4; e++) acc[im][in_][e] = 0.f;

    issue(0, 0);
    for (int ko = 0; ko < 8; ko++) {
        const int buf = ko & 1;
        if (ko + 1 < 8) {
            issue(ko + 1, buf ^ 1);
            asm volatile("cp.async.wait_group 1;");
        } else {
            asm volatile("cp.async.wait_group 0;");
        }
        __syncthreads();

        const __nv_bfloat16* st = smem + buf * STAGE_E;
        const __nv_bfloat16* Ap0 = st;
        const __nv_bfloat16* Ap1 = st + TILE_A_E;
        const __nv_bfloat16* Bp0 = st + 2 * TILE_A_E;
        const __nv_bfloat16* Bp1 = st + 2 * TILE_A_E + TILE_B_E;

#pragma unroll
        for (int ks = 0; ks < 4; ks++) {
            const int kofs = ks * 16;
            uint32_t a0f[4][4], a1f[4][4];
#pragma unroll
            for (int im = 0; im < 4; im++) {
                const int rb = wm * 64 + im * 16 + g;
                a0f[im][0] = *(const uint32_t*)(Ap0 + rb * TSTR + kofs + cq * 2);
                a0f[im][1] = *(const uint32_t*)(Ap0 + (rb + 8) * TSTR + kofs + cq * 2);
                a0f[im][2] = *(const uint32_t*)(Ap0 + rb * TSTR + kofs + 8 + cq * 2);
                a0f[im][3] = *(const uint32_t*)(Ap0 + (rb + 8) * TSTR + kofs + 8 + cq * 2);
                a1f[im][0] = *(const uint32_t*)(Ap1 + rb * TSTR + kofs + cq * 2);
                a1f[im][1] = *(const uint32_t*)(Ap1 + (rb + 8) * TSTR + kofs + cq * 2);
                a1f[im][2] = *(const uint32_t*)(Ap1 + rb * TSTR + kofs + 8 + cq * 2);
                a1f[im][3] = *(const uint32_t*)(Ap1 + (rb + 8) * TSTR + kofs + 8 + cq * 2);
            }
#pragma unroll
            for (int in_ = 0; in_ < 8; in_++) {
                const int nr = wn * 64 + in_ * 8 + g;
                const uint32_t b00 = *(const uint32_t*)(Bp0 + nr * TSTR + kofs + cq * 2);
                const uint32_t b01 = *(const uint32_t*)(Bp0 + nr * TSTR + kofs + 8 + cq * 2);
                const uint32_t b10 = *(const uint32_t*)(Bp1 + nr * TSTR + kofs + cq * 2);
                const uint32_t b11 = *(const uint32_t*)(Bp1 + nr * TSTR + kofs + 8 + cq * 2);
#pragma unroll
                for (int im = 0; im < 4; im++) {
                    mma16816(acc[im][in_], a0f[im], b00, b01);
                    mma16816(acc[im][in_], a0f[im], b10, b11);
                    mma16816(acc[im][in_], a1f[im], b00, b01);
                }
            }
        }
        __syncthreads();
    }

    // Epilogue
#pragma unroll
    for (int im = 0; im < 4; im++) {
#pragma unroll
        for (int in_ = 0; in_ < 8; in_++) {
            const int C0 = col0 + wn * 64 + in_ * 8 + cq * 2;
#pragma unroll
            for (int half = 0; half < 2; half++) {
                const int R = row0 + wm * 64 + im * 16 + g + half * 8;
                float vx = acc[im][in_][half * 2];
                float vy = acc[im][in_][half * 2 + 1];
                if (mode == 0) {
                    const int b2 = R >> 12, n2 = R & 4095;
                    const int w = n2 >> 5, jw = n2 & 31;
                    const int part = C0 >> 9;
                    const int h = (C0 & 511) >> 6;
                    const int dh = C0 & 63;
                    const size_t idx = (((size_t)((b2 * HH + h) * PP + jw)) * WW + w) * DH + dh;
                    uint32_t hi, lo;
                    pack_split(vx, vy, hi, lo);
                    __nv_bfloat16* d0 = (part == 0 ? g_q0 : part == 1 ? g_k0 : g_v0);
                    __nv_bfloat16* d1 = (part == 0 ? g_q1 : part == 1 ? g_k1 : g_v1);
                    *(uint32_t*)(d0 + idx) = hi;
                    *(uint32_t*)(d1 + idx) = lo;
                } else {
                    const int b2 = R >> 12, n2 = R & 4095;
                    const int dstn = (n2 + DISP) & 4095;
                    float2 v2;
                    v2.x = vx + __ldg(&bias[C0]);
                    v2.y = vy + __ldg(&bias[C0 + 1]);
                    *(float2*)(Out + (size_t)(b2 * NTOK + dstn) * DMODEL + C0) = v2;
                }
            }
        }
    }
}

// ---------------------------------------------------------------------------
// K2: tensor-core window attention (mask-split into two 64-key halves).
// ---------------------------------------------------------------------------
#define ATSTR 72
#define ATILE_E (WW*ATSTR)
#define ATILE_B (ATILE_E*2)
#define ATT_SMEM (1024 + 6*ATILE_B)          // 111616 B

__global__ __launch_bounds__(256) void attn_kernel(const float* __restrict__ pos_emb) {
    extern __shared__ char smem_raw[];
    float* slut = (float*)smem_raw;
    __nv_bfloat16* tiles = (__nv_bfloat16*)(smem_raw + 1024);

    const int bid = blockIdx.x;
    const int tid = threadIdx.x;
    const int wid = tid >> 5;
    const int lid = tid & 31;
    const int g = lid >> 2, cq = lid & 3;

    if (tid < 2 * WW - 1) slut[tid] = pos_emb[tid];

    const size_t woff = (size_t)bid * (WW * DH);
    const __nv_bfloat16* srcs[6] = { g_q0 + woff, g_q1 + woff, g_k0 + woff,
                                     g_k1 + woff, g_v0 + woff, g_v1 + woff };
#pragma unroll
    for (int arr = 0; arr < 6; arr++) {
        const __nv_bfloat16* src = srcs[arr];
        __nv_bfloat16* tb = tiles + arr * ATILE_E;
#pragma unroll
        for (int ii = 0; ii < 4; ii++) {
            const int idx = ii * 256 + tid;
            const int r = idx >> 3, c8 = idx & 7;
            const uint32_t dst = smem_u32(tb + r * ATSTR + c8 * 8);
            asm volatile("cp.async.cg.shared.global [%0], [%1], 16;"
                         :: "r"(dst), "l"(src + r * 64 + c8 * 8));
        }
    }
    asm volatile("cp.async.commit_group;");
    asm volatile("cp.async.wait_group 0;");
    __syncthreads();

    const __nv_bfloat16* sq0 = tiles;
    const __nv_bfloat16* sq1 = tiles + ATILE_E;
    const __nv_bfloat16* sk0 = tiles + 2 * ATILE_E;
    const __nv_bfloat16* sk1 = tiles + 3 * ATILE_E;
    const __nv_bfloat16* sv0 = tiles + 4 * ATILE_E;
    const __nv_bfloat16* sv1 = tiles + 5 * ATILE_E;

    const int half = wid >> 2;
    const int mrow = (wid & 3) * 16;
    const int qrow0 = half * 64 + mrow;
    const int kbase = half * 64;

    float S[8][4];
#pragma unroll
    for (int nt = 0; nt < 8; nt++)
#pragma unroll
        for (int e = 0; e < 4; e++) S[nt][e] = 0.f;

#pragma unroll
    for (int ks = 0; ks < 4; ks++) {
        const int k0 = ks * 16;
        uint32_t aq0[4], aq1[4];
        aq0[0] = *(const uint32_t*)(sq0 + (qrow0 + g) * ATSTR + k0 + cq * 2);
        aq0[1] = *(const uint32_t*)(sq0 + (qrow0 + g + 8) * ATSTR + k0 + cq * 2);
        aq0[2] = *(const uint32_t*)(sq0 + (qrow0 + g) * ATSTR + k0 + 8 + cq * 2);
        aq0[3] = *(const uint32_t*)(sq0 + (qrow0 + g + 8) * ATSTR + k0 + 8 + cq * 2);
        aq1[0] = *(const uint32_t*)(sq1 + (qrow0 + g) * ATSTR + k0 + cq * 2);
        aq1[1] = *(const uint32_t*)(sq1 + (qrow0 + g + 8) * ATSTR + k0 + cq * 2);
        aq1[2] = *(const uint32_t*)(sq1 + (qrow0 + g) * ATSTR + k0 + 8 + cq * 2);
        aq1[3] = *(const uint32_t*)(sq1 + (qrow0 + g + 8) * ATSTR + k0 + 8 + cq * 2);
#pragma unroll
        for (int nt = 0; nt < 8; nt++) {
            const int krow = kbase + nt * 8 + g;
            const uint32_t b00 = *(const uint32_t*)(sk0 + krow * ATSTR + k0 + cq * 2);
            const uint32_t b01 = *(const uint32_t*)(sk0 + krow * ATSTR + k0 + 8 + cq * 2);
            const uint32_t b10 = *(const uint32_t*)(sk1 + krow * ATSTR + k0 + cq * 2);
            const uint32_t b11 = *(const uint32_t*)(sk1 + krow * ATSTR + k0 + 8 + cq * 2);
            mma16816(S[nt], aq0, b00, b01);
            mma16816(S[nt], aq0, b10, b11);
            mma16816(S[nt], aq1, b00, b01);
        }
    }

    const float scale = 0.125f;
    const int il0 = mrow + g;
    const int il1 = il0 + 8;
    float rs0 = 0.f, rs1 = 0.f;
#pragma unroll
    for (int nt = 0; nt < 8; nt++) {
        const int jl = nt * 8 + cq * 2;
        float p0 = __expf(S[nt][0] * scale + slut[jl - il0 + (WW - 1)]);
        float p1 = __expf(S[nt][1] * scale + slut[jl + 1 - il0 + (WW - 1)]);
        float p2 = __expf(S[nt][2] * scale + slut[jl - il1 + (WW - 1)]);
        float p3 = __expf(S[nt][3] * scale + slut[jl + 1 - il1 + (WW - 1)]);
        S[nt][0] = p0; S[nt][1] = p1; S[nt][2] = p2; S[nt][3] = p3;
        rs0 += p0 + p1;
        rs1 += p2 + p3;
    }
    rs0 += __shfl_xor_sync(0xFFFFFFFF, rs0, 1);
    rs0 += __shfl_xor_sync(0xFFFFFFFF, rs0, 2);
    rs1 += __shfl_xor_sync(0xFFFFFFFF, rs1, 1);
    rs1 += __shfl_xor_sync(0xFFFFFFFF, rs1, 2);
    const float inv0 = 1.0f / rs0;
    const float inv1 = 1.0f / rs1;

    uint32_t p0f[4][4], p1f[4][4];
#pragma unroll
    for (int ks = 0; ks < 4; ks++) {
        pack_split(S[2 * ks][0],     S[2 * ks][1],     p0f[ks][0], p1f[ks][0]);
        pack_split(S[2 * ks][2],     S[2 * ks][3],     p0f[ks][1], p1f[ks][1]);
        pack_split(S[2 * ks + 1][0], S[2 * ks + 1][1], p0f[ks][2], p1f[ks][2]);
        pack_split(S[2 * ks + 1][2], S[2 * ks + 1][3], p0f[ks][3], p1f[ks][3]);
    }

    float O[8][4];
#pragma unroll
    for (int nt = 0; nt < 8; nt++)
#pragma unroll
        for (int e = 0; e < 4; e++) O[nt][e] = 0.f;

#pragma unroll
    for (int ks = 0; ks < 4; ks++) {
        const int vrow = kbase + ks * 16 + (lid & 15);
#pragma unroll
        for (int nt = 0; nt < 8; nt++) {
            uint32_t vb00, vb01, vb10, vb11;
            ldsm_x2_trans(vb00, vb01, smem_u32(sv0 + vrow * ATSTR + nt * 8));
            ldsm_x2_trans(vb10, vb11, smem_u32(sv1 + vrow * ATSTR + nt * 8));
            mma16816(O[nt], p0f[ks], vb00, vb01);
            mma16816(O[nt], p0f[ks], vb10, vb11);
            mma16816(O[nt], p1f[ks], vb00, vb01);
        }
    }

    const int b  = bid >> 8;
    const int h  = (bid >> 5) & 7;
    const int jw = bid & 31;
    const int iw0 = half * 64 + il0;
    const int iw1 = half * 64 + il1;
    const size_t row0off = ((size_t)(b * NTOK + jw * WW + iw0)) * DMODEL + h * DH;
    const size_t row1off = ((size_t)(b * NTOK + jw * WW + iw1)) * DMODEL + h * DH;
#pragma unroll
    for (int nt = 0; nt < 8; nt++) {
        const int c = nt * 8 + cq * 2;
        uint32_t hi, lo;
        pack_split(O[nt][0] * inv0, O[nt][1] * inv0, hi, lo);
        *(uint32_t*)(g_ao0 + row0off + c) = hi;
        *(uint32_t*)(g_ao1 + row0off + c) = lo;
        pack_split(O[nt][2] * inv1, O[nt][3] * inv1, hi, lo);
        *(uint32_t*)(g_ao0 + row1off + c) = hi;
        *(uint32_t*)(g_ao1 + row1off + c) = lo;
    }
}

// ---------------------------------------------------------------------------
extern "C" void kernel_launch(void* const* d_in, const int* in_sizes, int n_in,
                              void* d_out, int out_size) {
    const float* x       = (const float*)d_in[0];
    const float* Wqkv    = (const float*)d_in[1];
    const float* pos_emb = (const float*)d_in[2];
    const float* Wout    = (const float*)d_in[3];
    const float* bout    = (const float*)d_in[4];
    float* out = (float*)d_out;

    cudaFuncSetAttribute(gemm256, cudaFuncAttributeMaxDynamicSharedMemorySize, GEMM_SMEM);
    cudaFuncSetAttribute(attn_kernel, cudaFuncAttributeMaxDynamicSharedMemorySize, ATT_SMEM);

    conv_x_kernel<<<(BB * NTOK * DMODEL + 255) / 256, 256>>>(x);
    conv_w_kernel<<<(1536 * 512 + 255) / 256, 256>>>(Wqkv, 1536, 0);
    conv_w_kernel<<<(512 * 512 + 255) / 256, 256>>>(Wout, 512, 1);

    // K1: QKV (M=32768 -> 128 row blocks, N=1536 -> 12 col blocks)
    gemm256<<<dim3(12, 128), 256, GEMM_SMEM>>>(nullptr, nullptr, 0);
    // K2: attention, one window per block
    attn_kernel<<<2048, 256, ATT_SMEM>>>(pos_emb);
    // K3: output projection (N=512 -> 4 col blocks) + bias + roll
    gemm256<<<dim3(4, 128), 256, GEMM_SMEM>>>(bout, out, 1);
}

// round 8
// speedup vs baseline: 1.9469x; 1.2545x over previous
#include <cuda_runtime.h>
#include <cuda_bf16.h>
#include <cuda_fp16.h>
#include <cstdint>

// Problem constants
#define BB   8
#define NTOK 4096
#define DMODEL 512
#define HH   8
#define DH   64
#define WW   128
#define PP   32
#define DISP 64

// ---------------------------------------------------------------------------
// Scratch (__device__ globals; allocation-free rule)
// ---------------------------------------------------------------------------
// q/k/v window layout, bf16x2 split (consumed by bf16 3-pass attention)
__device__ __nv_bfloat16 g_q0[BB*HH*PP*WW*DH];
__device__ __nv_bfloat16 g_q1[BB*HH*PP*WW*DH];
__device__ __nv_bfloat16 g_k0[BB*HH*PP*WW*DH];
__device__ __nv_bfloat16 g_k1[BB*HH*PP*WW*DH];
__device__ __nv_bfloat16 g_v0[BB*HH*PP*WW*DH];
__device__ __nv_bfloat16 g_v1[BB*HH*PP*WW*DH];
// fp16 pair split of rolled X [32768, 512]
__device__ __half g_xa0[BB*NTOK*DMODEL];
__device__ __half g_xa1[BB*NTOK*DMODEL];
// single-fp16 Wqkv^T [1536, 512] and Wout^T [512, 512]
__device__ __half g_wq[3*HH*DH*DMODEL];
__device__ __half g_wo[DMODEL*DMODEL];
// fp16 pair split of attention output (token layout, shifted) [32768, 512]
__device__ __half g_ao0[BB*NTOK*DMODEL];
__device__ __half g_ao1[BB*NTOK*DMODEL];

__device__ __forceinline__ uint32_t smem_u32(const void* p) {
    uint32_t a;
    asm("{ .reg .u64 t; cvta.to.shared.u64 t, %1; cvt.u32.u64 %0, t; }"
        : "=r"(a) : "l"(p));
    return a;
}
// bf16 mma (attention)
__device__ __forceinline__ void mma16816(float* d, const uint32_t* a,
                                         uint32_t b0, uint32_t b1) {
    asm volatile(
        "mma.sync.aligned.m16n8k16.row.col.f32.bf16.bf16.f32 "
        "{%0,%1,%2,%3}, {%4,%5,%6,%7}, {%8,%9}, {%0,%1,%2,%3};"
        : "+f"(d[0]), "+f"(d[1]), "+f"(d[2]), "+f"(d[3])
        : "r"(a[0]), "r"(a[1]), "r"(a[2]), "r"(a[3]), "r"(b0), "r"(b1));
}
// fp16 mma (projections)
__device__ __forceinline__ void mma16816h(float* d, const uint32_t* a,
                                          uint32_t b0, uint32_t b1) {
    asm volatile(
        "mma.sync.aligned.m16n8k16.row.col.f32.f16.f16.f32 "
        "{%0,%1,%2,%3}, {%4,%5,%6,%7}, {%8,%9}, {%0,%1,%2,%3};"
        : "+f"(d[0]), "+f"(d[1]), "+f"(d[2]), "+f"(d[3])
        : "r"(a[0]), "r"(a[1]), "r"(a[2]), "r"(a[3]), "r"(b0), "r"(b1));
}
__device__ __forceinline__ void ldsm_x2_trans(uint32_t& r0, uint32_t& r1, uint32_t addr) {
    asm volatile("ldmatrix.sync.aligned.m8n8.x2.trans.shared.b16 {%0,%1}, [%2];"
                 : "=r"(r0), "=r"(r1) : "r"(addr));
}
// bf16 pair split pack
__device__ __forceinline__ void pack_split(float x, float y, uint32_t& hi, uint32_t& lo) {
    __nv_bfloat16 hx = __float2bfloat16(x), hy = __float2bfloat16(y);
    float rx = x - __bfloat162float(hx), ry = y - __bfloat162float(hy);
    __nv_bfloat162 h; h.x = hx; h.y = hy;
    __nv_bfloat162 l; l.x = __float2bfloat16(rx); l.y = __float2bfloat16(ry);
    hi = *(uint32_t*)&h; lo = *(uint32_t*)&l;
}
// fp16 pair split pack
__device__ __forceinline__ void pack_split_h(float x, float y, uint32_t& hi, uint32_t& lo) {
    __half hx = __float2half_rn(x), hy = __float2half_rn(y);
    float rx = x - __half2float(hx), ry = y - __half2float(hy);
    __half2 h; h.x = hx; h.y = hy;
    __half2 l; l.x = __float2half_rn(rx); l.y = __float2half_rn(ry);
    hi = *(uint32_t*)&h; lo = *(uint32_t*)&l;
}

// ---------------------------------------------------------------------------
// Prepass: X -> fp16 pair (roll fused); W -> transpose + single fp16
// ---------------------------------------------------------------------------
__global__ __launch_bounds__(256) void conv_x_kernel(const float* __restrict__ X) {
    int idx = blockIdx.x * 256 + threadIdx.x;
    if (idx >= BB * NTOK * DMODEL) return;
    int r = idx >> 9, k = idx & 511;
    int b = r >> 12, n = r & 4095;
    float v = X[(size_t)(b * NTOK + ((n + DISP) & 4095)) * DMODEL + k];
    __half h0 = __float2half_rn(v);
    g_xa0[idx] = h0;
    g_xa1[idx] = __float2half_rn(v - __half2float(h0));
}

__global__ __launch_bounds__(256) void conv_w_kernel(const float* __restrict__ src,
                                                     int N, int which) {
    int idx = blockIdx.x * 256 + threadIdx.x;
    if (idx >= N * DMODEL) return;
    int n = idx >> 9, k = idx & 511;
    float v = src[(size_t)k * N + n];
    if (which == 0) g_wq[idx] = __float2half_rn(v);
    else            g_wo[idx] = __float2half_rn(v);
}

// ---------------------------------------------------------------------------
// fp16 2-pass mma.sync GEMM: C = (A0 + A1) @ B^T, block tile 256x128,
// 8 warps (4x2) of 64x64 each. K=512 in 8 chunks of 64, 2-stage cp.async.
// mode 0: Xr @ Wqkv -> scatter bf16x2 q/k/v window layout
// mode 1: AO @ Wout (+bias) -> d_out with roll(+DISP)
// ---------------------------------------------------------------------------
#define KCH   64
#define TSTR  72
#define TILE_A_E (256*TSTR)                 // 18432 elems per A array
#define TILE_B_E (128*TSTR)                 // 9216 elems
#define STAGE_E  (2*TILE_A_E + TILE_B_E)    // 46080 elems
#define GEMM_SMEM (2*STAGE_E*2)             // 184320 B

__global__ __launch_bounds__(256) void gemm256(const float* __restrict__ bias,
                                               float* __restrict__ Out, int mode) {
    extern __shared__ char smem_raw[];
    __half* smem = (__half*)smem_raw;
    const int tid = threadIdx.x;
    const int wid = tid >> 5;
    const int lid = tid & 31;
    const int row0 = blockIdx.y * 256;
    const int col0 = blockIdx.x * 128;
    const int wm = wid & 3, wn = wid >> 2;
    const int g = lid >> 2, cq = lid & 3;

    const __half* A0 = mode ? g_ao0 : g_xa0;
    const __half* A1 = mode ? g_ao1 : g_xa1;
    const __half* Bw = mode ? g_wo : g_wq;

    // one 64-wide k-chunk: A pair 4096 16B-chunks + B 1024 = 5120
    auto issue = [&](int ko, int buf) {
        const int kbase = ko * KCH;
        __half* st = smem + buf * STAGE_E;
#pragma unroll
        for (int i = 0; i < 20; i++) {
            const int cidx = tid + i * 256;          // 0..5119
            const __half* src;
            uint32_t dst;
            if (cidx < 4096) {
                const int arr = cidx >> 11;
                const int r = (cidx >> 3) & 255;
                const int c8 = cidx & 7;
                src = (arr ? A1 : A0) + (size_t)(row0 + r) * 512 + kbase + c8 * 8;
                dst = smem_u32(st + arr * TILE_A_E + r * TSTR + c8 * 8);
            } else {
                const int rem = cidx - 4096;
                const int r = rem >> 3;
                const int c8 = rem & 7;
                src = Bw + (size_t)(col0 + r) * 512 + kbase + c8 * 8;
                dst = smem_u32(st + 2 * TILE_A_E + r * TSTR + c8 * 8);
            }
            asm volatile("cp.async.cg.shared.global [%0], [%1], 16;"
                         :: "r"(dst), "l"(src));
        }
        asm volatile("cp.async.commit_group;");
    };

    float acc[4][8][4];
#pragma unroll
    for (int im = 0; im < 4; im++)
#pragma unroll
        for (int in_ = 0; in_ < 8; in_++)
#pragma unroll
            for (int e = 0; e < 4; e++) acc[im][in_][e] = 0.f;

    issue(0, 0);
    for (int ko = 0; ko < 8; ko++) {
        const int buf = ko & 1;
        if (ko + 1 < 8) {
            issue(ko + 1, buf ^ 1);
            asm volatile("cp.async.wait_group 1;");
        } else {
            asm volatile("cp.async.wait_group 0;");
        }
        __syncthreads();

        const __half* st = smem + buf * STAGE_E;
        const __half* Ap0 = st;
        const __half* Ap1 = st + TILE_A_E;
        const __half* Bp  = st + 2 * TILE_A_E;

#pragma unroll
        for (int ks = 0; ks < 4; ks++) {
            const int kofs = ks * 16;
            uint32_t a0f[4][4], a1f[4][4];
#pragma unroll
            for (int im = 0; im < 4; im++) {
                const int rb = wm * 64 + im * 16 + g;
                a0f[im][0] = *(const uint32_t*)(Ap0 + rb * TSTR + kofs + cq * 2);
                a0f[im][1] = *(const uint32_t*)(Ap0 + (rb + 8) * TSTR + kofs + cq * 2);
                a0f[im][2] = *(const uint32_t*)(Ap0 + rb * TSTR + kofs + 8 + cq * 2);
                a0f[im][3] = *(const uint32_t*)(Ap0 + (rb + 8) * TSTR + kofs + 8 + cq * 2);
                a1f[im][0] = *(const uint32_t*)(Ap1 + rb * TSTR + kofs + cq * 2);
                a1f[im][1] = *(const uint32_t*)(Ap1 + (rb + 8) * TSTR + kofs + cq * 2);
                a1f[im][2] = *(const uint32_t*)(Ap1 + rb * TSTR + kofs + 8 + cq * 2);
                a1f[im][3] = *(const uint32_t*)(Ap1 + (rb + 8) * TSTR + kofs + 8 + cq * 2);
            }
#pragma unroll
            for (int in_ = 0; in_ < 8; in_++) {
                const int nr = wn * 64 + in_ * 8 + g;
                const uint32_t b0 = *(const uint32_t*)(Bp + nr * TSTR + kofs + cq * 2);
                const uint32_t b1 = *(const uint32_t*)(Bp + nr * TSTR + kofs + 8 + cq * 2);
#pragma unroll
                for (int im = 0; im < 4; im++) {
                    mma16816h(acc[im][in_], a0f[im], b0, b1);
                    mma16816h(acc[im][in_], a1f[im], b0, b1);
                }
            }
        }
        __syncthreads();
    }

    // Epilogue
#pragma unroll
    for (int im = 0; im < 4; im++) {
#pragma unroll
        for (int in_ = 0; in_ < 8; in_++) {
            const int C0 = col0 + wn * 64 + in_ * 8 + cq * 2;
#pragma unroll
            for (int half = 0; half < 2; half++) {
                const int R = row0 + wm * 64 + im * 16 + g + half * 8;
                float vx = acc[im][in_][half * 2];
                float vy = acc[im][in_][half * 2 + 1];
                if (mode == 0) {
                    const int b2 = R >> 12, n2 = R & 4095;
                    const int w = n2 >> 5, jw = n2 & 31;
                    const int part = C0 >> 9;
                    const int h = (C0 & 511) >> 6;
                    const int dh = C0 & 63;
                    const size_t idx = (((size_t)((b2 * HH + h) * PP + jw)) * WW + w) * DH + dh;
                    uint32_t hi, lo;
                    pack_split(vx, vy, hi, lo);
                    __nv_bfloat16* d0 = (part == 0 ? g_q0 : part == 1 ? g_k0 : g_v0);
                    __nv_bfloat16* d1 = (part == 0 ? g_q1 : part == 1 ? g_k1 : g_v1);
                    *(uint32_t*)(d0 + idx) = hi;
                    *(uint32_t*)(d1 + idx) = lo;
                } else {
                    const int b2 = R >> 12, n2 = R & 4095;
                    const int dstn = (n2 + DISP) & 4095;
                    float2 v2;
                    v2.x = vx + __ldg(&bias[C0]);
                    v2.y = vy + __ldg(&bias[C0 + 1]);
                    *(float2*)(Out + (size_t)(b2 * NTOK + dstn) * DMODEL + C0) = v2;
                }
            }
        }
    }
}

// ---------------------------------------------------------------------------
// K2: tensor-core window attention (mask-split into two 64-key halves),
// bf16 3-pass. Epilogue emits fp16 pair for K3.
// ---------------------------------------------------------------------------
#define ATSTR 72
#define ATILE_E (WW*ATSTR)
#define ATILE_B (ATILE_E*2)
#define ATT_SMEM (1024 + 6*ATILE_B)          // 111616 B

__global__ __launch_bounds__(256) void attn_kernel(const float* __restrict__ pos_emb) {
    extern __shared__ char smem_raw[];
    float* slut = (float*)smem_raw;
    __nv_bfloat16* tiles = (__nv_bfloat16*)(smem_raw + 1024);

    const int bid = blockIdx.x;
    const int tid = threadIdx.x;
    const int wid = tid >> 5;
    const int lid = tid & 31;
    const int g = lid >> 2, cq = lid & 3;

    if (tid < 2 * WW - 1) slut[tid] = pos_emb[tid];

    const size_t woff = (size_t)bid * (WW * DH);
    const __nv_bfloat16* srcs[6] = { g_q0 + woff, g_q1 + woff, g_k0 + woff,
                                     g_k1 + woff, g_v0 + woff, g_v1 + woff };
#pragma unroll
    for (int arr = 0; arr < 6; arr++) {
        const __nv_bfloat16* src = srcs[arr];
        __nv_bfloat16* tb = tiles + arr * ATILE_E;
#pragma unroll
        for (int ii = 0; ii < 4; ii++) {
            const int idx = ii * 256 + tid;
            const int r = idx >> 3, c8 = idx & 7;
            const uint32_t dst = smem_u32(tb + r * ATSTR + c8 * 8);
            asm volatile("cp.async.cg.shared.global [%0], [%1], 16;"
                         :: "r"(dst), "l"(src + r * 64 + c8 * 8));
        }
    }
    asm volatile("cp.async.commit_group;");
    asm volatile("cp.async.wait_group 0;");
    __syncthreads();

    const __nv_bfloat16* sq0 = tiles;
    const __nv_bfloat16* sq1 = tiles + ATILE_E;
    const __nv_bfloat16* sk0 = tiles + 2 * ATILE_E;
    const __nv_bfloat16* sk1 = tiles + 3 * ATILE_E;
    const __nv_bfloat16* sv0 = tiles + 4 * ATILE_E;
    const __nv_bfloat16* sv1 = tiles + 5 * ATILE_E;

    const int half = wid >> 2;
    const int mrow = (wid & 3) * 16;
    const int qrow0 = half * 64 + mrow;
    const int kbase = half * 64;

    float S[8][4];
#pragma unroll
    for (int nt = 0; nt < 8; nt++)
#pragma unroll
        for (int e = 0; e < 4; e++) S[nt][e] = 0.f;

#pragma unroll
    for (int ks = 0; ks < 4; ks++) {
        const int k0 = ks * 16;
        uint32_t aq0[4], aq1[4];
        aq0[0] = *(const uint32_t*)(sq0 + (qrow0 + g) * ATSTR + k0 + cq * 2);
        aq0[1] = *(const uint32_t*)(sq0 + (qrow0 + g + 8) * ATSTR + k0 + cq * 2);
        aq0[2] = *(const uint32_t*)(sq0 + (qrow0 + g) * ATSTR + k0 + 8 + cq * 2);
        aq0[3] = *(const uint32_t*)(sq0 + (qrow0 + g + 8) * ATSTR + k0 + 8 + cq * 2);
        aq1[0] = *(const uint32_t*)(sq1 + (qrow0 + g) * ATSTR + k0 + cq * 2);
        aq1[1] = *(const uint32_t*)(sq1 + (qrow0 + g + 8) * ATSTR + k0 + cq * 2);
        aq1[2] = *(const uint32_t*)(sq1 + (qrow0 + g) * ATSTR + k0 + 8 + cq * 2);
        aq1[3] = *(const uint32_t*)(sq1 + (qrow0 + g + 8) * ATSTR + k0 + 8 + cq * 2);
#pragma unroll
        for (int nt = 0; nt < 8; nt++) {
            const int krow = kbase + nt * 8 + g;
            const uint32_t b00 = *(const uint32_t*)(sk0 + krow * ATSTR + k0 + cq * 2);
            const uint32_t b01 = *(const uint32_t*)(sk0 + krow * ATSTR + k0 + 8 + cq * 2);
            const uint32_t b10 = *(const uint32_t*)(sk1 + krow * ATSTR + k0 + cq * 2);
            const uint32_t b11 = *(const uint32_t*)(sk1 + krow * ATSTR + k0 + 8 + cq * 2);
            mma16816(S[nt], aq0, b00, b01);
            mma16816(S[nt], aq0, b10, b11);
            mma16816(S[nt], aq1, b00, b01);
        }
    }

    const float scale = 0.125f;
    const int il0 = mrow + g;
    const int il1 = il0 + 8;
    float rs0 = 0.f, rs1 = 0.f;
#pragma unroll
    for (int nt = 0; nt < 8; nt++) {
        const int jl = nt * 8 + cq * 2;
        float p0 = __expf(S[nt][0] * scale + slut[jl - il0 + (WW - 1)]);
        float p1 = __expf(S[nt][1] * scale + slut[jl + 1 - il0 + (WW - 1)]);
        float p2 = __expf(S[nt][2] * scale + slut[jl - il1 + (WW - 1)]);
        float p3 = __expf(S[nt][3] * scale + slut[jl + 1 - il1 + (WW - 1)]);
        S[nt][0] = p0; S[nt][1] = p1; S[nt][2] = p2; S[nt][3] = p3;
        rs0 += p0 + p1;
        rs1 += p2 + p3;
    }
    rs0 += __shfl_xor_sync(0xFFFFFFFF, rs0, 1);
    rs0 += __shfl_xor_sync(0xFFFFFFFF, rs0, 2);
    rs1 += __shfl_xor_sync(0xFFFFFFFF, rs1, 1);
    rs1 += __shfl_xor_sync(0xFFFFFFFF, rs1, 2);
    const float inv0 = 1.0f / rs0;
    const float inv1 = 1.0f / rs1;

    uint32_t p0f[4][4], p1f[4][4];
#pragma unroll
    for (int ks = 0; ks < 4; ks++) {
        pack_split(S[2 * ks][0],     S[2 * ks][1],     p0f[ks][0], p1f[ks][0]);
        pack_split(S[2 * ks][2],     S[2 * ks][3],     p0f[ks][1], p1f[ks][1]);
        pack_split(S[2 * ks + 1][0], S[2 * ks + 1][1], p0f[ks][2], p1f[ks][2]);
        pack_split(S[2 * ks + 1][2], S[2 * ks + 1][3], p0f[ks][3], p1f[ks][3]);
    }

    float O[8][4];
#pragma unroll
    for (int nt = 0; nt < 8; nt++)
#pragma unroll
        for (int e = 0; e < 4; e++) O[nt][e] = 0.f;

#pragma unroll
    for (int ks = 0; ks < 4; ks++) {
        const int vrow = kbase + ks * 16 + (lid & 15);
#pragma unroll
        for (int nt = 0; nt < 8; nt++) {
            uint32_t vb00, vb01, vb10, vb11;
            ldsm_x2_trans(vb00, vb01, smem_u32(sv0 + vrow * ATSTR + nt * 8));
            ldsm_x2_trans(vb10, vb11, smem_u32(sv1 + vrow * ATSTR + nt * 8));
            mma16816(O[nt], p0f[ks], vb00, vb01);
            mma16816(O[nt], p0f[ks], vb10, vb11);
            mma16816(O[nt], p1f[ks], vb00, vb01);
        }
    }

    const int b  = bid >> 8;
    const int h  = (bid >> 5) & 7;
    const int jw = bid & 31;
    const int iw0 = half * 64 + il0;
    const int iw1 = half * 64 + il1;
    const size_t row0off = ((size_t)(b * NTOK + jw * WW + iw0)) * DMODEL + h * DH;
    const size_t row1off = ((size_t)(b * NTOK + jw * WW + iw1)) * DMODEL + h * DH;
#pragma unroll
    for (int nt = 0; nt < 8; nt++) {
        const int c = nt * 8 + cq * 2;
        uint32_t hi, lo;
        pack_split_h(O[nt][0] * inv0, O[nt][1] * inv0, hi, lo);
        *(uint32_t*)(g_ao0 + row0off + c) = hi;
        *(uint32_t*)(g_ao1 + row0off + c) = lo;
        pack_split_h(O[nt][2] * inv1, O[nt][3] * inv1, hi, lo);
        *(uint32_t*)(g_ao0 + row1off + c) = hi;
        *(uint32_t*)(g_ao1 + row1off + c) = lo;
    }
}

// ---------------------------------------------------------------------------
extern "C" void kernel_launch(void* const* d_in, const int* in_sizes, int n_in,
                              void* d_out, int out_size) {
    const float* x       = (const float*)d_in[0];
    const float* Wqkv    = (const float*)d_in[1];
    const float* pos_emb = (const float*)d_in[2];
    const float* Wout    = (const float*)d_in[3];
    const float* bout    = (const float*)d_in[4];
    float* out = (float*)d_out;

    cudaFuncSetAttribute(gemm256, cudaFuncAttributeMaxDynamicSharedMemorySize, GEMM_SMEM);
    cudaFuncSetAttribute(attn_kernel, cudaFuncAttributeMaxDynamicSharedMemorySize, ATT_SMEM);

    conv_x_kernel<<<(BB * NTOK * DMODEL + 255) / 256, 256>>>(x);
    conv_w_kernel<<<(1536 * 512 + 255) / 256, 256>>>(Wqkv, 1536, 0);
    conv_w_kernel<<<(512 * 512 + 255) / 256, 256>>>(Wout, 512, 1);

    // K1: QKV (M=32768 -> 128 row blocks, N=1536 -> 12 col blocks)
    gemm256<<<dim3(12, 128), 256, GEMM_SMEM>>>(nullptr, nullptr, 0);
    // K2: attention, one window per block
    attn_kernel<<<2048, 256, ATT_SMEM>>>(pos_emb);
    // K3: output projection (N=512 -> 4 col blocks) + bias + roll
    gemm256<<<dim3(4, 128), 256, GEMM_SMEM>>>(bout, out, 1);
}

// round 9
// speedup vs baseline: 2.8277x; 1.4524x over previous
#include <cuda_runtime.h>
#include <cuda_bf16.h>
#include <cuda_fp16.h>
#include <cstdint>

// Problem constants
#define BB   8
#define NTOK 4096
#define DMODEL 512
#define HH   8
#define DH   64
#define WW   128
#define PP   32
#define DISP 64

// ---------------------------------------------------------------------------
// Scratch (__device__ globals; allocation-free rule)
// ---------------------------------------------------------------------------
// q/k/v window layout, bf16x2 split (consumed by bf16 3-pass attention)
__device__ __nv_bfloat16 g_q0[BB*HH*PP*WW*DH];
__device__ __nv_bfloat16 g_q1[BB*HH*PP*WW*DH];
__device__ __nv_bfloat16 g_k0[BB*HH*PP*WW*DH];
__device__ __nv_bfloat16 g_k1[BB*HH*PP*WW*DH];
__device__ __nv_bfloat16 g_v0[BB*HH*PP*WW*DH];
__device__ __nv_bfloat16 g_v1[BB*HH*PP*WW*DH];
// single fp16 rolled X [32768, 512]
__device__ __half g_xa[BB*NTOK*DMODEL];
// single fp16 Wqkv^T [1536, 512] and Wout^T [512, 512]
__device__ __half g_wq[3*HH*DH*DMODEL];
__device__ __half g_wo[DMODEL*DMODEL];
// single fp16 attention output (token layout, shifted) [32768, 512]
__device__ __half g_ao[BB*NTOK*DMODEL];

__device__ __forceinline__ uint32_t smem_u32(const void* p) {
    uint32_t a;
    asm("{ .reg .u64 t; cvta.to.shared.u64 t, %1; cvt.u32.u64 %0, t; }"
        : "=r"(a) : "l"(p));
    return a;
}
// bf16 mma (attention)
__device__ __forceinline__ void mma16816(float* d, const uint32_t* a,
                                         uint32_t b0, uint32_t b1) {
    asm volatile(
        "mma.sync.aligned.m16n8k16.row.col.f32.bf16.bf16.f32 "
        "{%0,%1,%2,%3}, {%4,%5,%6,%7}, {%8,%9}, {%0,%1,%2,%3};"
        : "+f"(d[0]), "+f"(d[1]), "+f"(d[2]), "+f"(d[3])
        : "r"(a[0]), "r"(a[1]), "r"(a[2]), "r"(a[3]), "r"(b0), "r"(b1));
}
// fp16 mma (projections)
__device__ __forceinline__ void mma16816h(float* d, const uint32_t* a,
                                          uint32_t b0, uint32_t b1) {
    asm volatile(
        "mma.sync.aligned.m16n8k16.row.col.f32.f16.f16.f32 "
        "{%0,%1,%2,%3}, {%4,%5,%6,%7}, {%8,%9}, {%0,%1,%2,%3};"
        : "+f"(d[0]), "+f"(d[1]), "+f"(d[2]), "+f"(d[3])
        : "r"(a[0]), "r"(a[1]), "r"(a[2]), "r"(a[3]), "r"(b0), "r"(b1));
}
__device__ __forceinline__ void ldsm_x2_trans(uint32_t& r0, uint32_t& r1, uint32_t addr) {
    asm volatile("ldmatrix.sync.aligned.m8n8.x2.trans.shared.b16 {%0,%1}, [%2];"
                 : "=r"(r0), "=r"(r1) : "r"(addr));
}
// bf16 pair split pack
__device__ __forceinline__ void pack_split(float x, float y, uint32_t& hi, uint32_t& lo) {
    __nv_bfloat16 hx = __float2bfloat16(x), hy = __float2bfloat16(y);
    float rx = x - __bfloat162float(hx), ry = y - __bfloat162float(hy);
    __nv_bfloat162 h; h.x = hx; h.y = hy;
    __nv_bfloat162 l; l.x = __float2bfloat16(rx); l.y = __float2bfloat16(ry);
    hi = *(uint32_t*)&h; lo = *(uint32_t*)&l;
}
__device__ __forceinline__ uint32_t pack_h2(float x, float y) {
    __half2 h; h.x = __float2half_rn(x); h.y = __float2half_rn(y);
    return *(uint32_t*)&h;
}

// ---------------------------------------------------------------------------
// Prepass: X -> fp16 (roll fused); W -> transpose + fp16
// ---------------------------------------------------------------------------
__global__ __launch_bounds__(256) void conv_x_kernel(const float* __restrict__ X) {
    int idx = blockIdx.x * 256 + threadIdx.x;
    if (idx >= BB * NTOK * DMODEL) return;
    int r = idx >> 9, k = idx & 511;
    int b = r >> 12, n = r & 4095;
    float v = X[(size_t)(b * NTOK + ((n + DISP) & 4095)) * DMODEL + k];
    g_xa[idx] = __float2half_rn(v);
}

__global__ __launch_bounds__(256) void conv_w_kernel(const float* __restrict__ src,
                                                     int N, int which) {
    int idx = blockIdx.x * 256 + threadIdx.x;
    if (idx >= N * DMODEL) return;
    int n = idx >> 9, k = idx & 511;
    float v = src[(size_t)k * N + n];
    if (which == 0) g_wq[idx] = __float2half_rn(v);
    else            g_wo[idx] = __float2half_rn(v);
}

// ---------------------------------------------------------------------------
// single-pass fp16 mma.sync GEMM: C = A @ B^T, block tile 256x128,
// 8 warps (4x2) of 64x64 each. K=512 in 8 chunks of 64, 2-stage cp.async.
// mode 0: Xr @ Wqkv -> scatter bf16x2 q/k/v window layout
// mode 1: AO @ Wout (+bias) -> d_out with roll(+DISP)
// ---------------------------------------------------------------------------
#define KCH   64
#define TSTR  72
#define TILE_A_E (256*TSTR)                 // 18432 elems
#define TILE_B_E (128*TSTR)                 // 9216 elems
#define STAGE_E  (TILE_A_E + TILE_B_E)      // 27648 elems
#define GEMM_SMEM (2*STAGE_E*2)             // 110592 B

__global__ __launch_bounds__(256) void gemm256(const float* __restrict__ bias,
                                               float* __restrict__ Out, int mode) {
    extern __shared__ char smem_raw[];
    __half* smem = (__half*)smem_raw;
    const int tid = threadIdx.x;
    const int wid = tid >> 5;
    const int lid = tid & 31;
    const int row0 = blockIdx.y * 256;
    const int col0 = blockIdx.x * 128;
    const int wm = wid & 3, wn = wid >> 2;
    const int g = lid >> 2, cq = lid & 3;

    const __half* A  = mode ? g_ao : g_xa;
    const __half* Bw = mode ? g_wo : g_wq;

    // one 64-wide k-chunk: A 2048 16B-chunks + B 1024 = 3072
    auto issue = [&](int ko, int buf) {
        const int kbase = ko * KCH;
        __half* st = smem + buf * STAGE_E;
#pragma unroll
        for (int i = 0; i < 12; i++) {
            const int cidx = tid + i * 256;          // 0..3071
            const __half* src;
            uint32_t dst;
            if (cidx < 2048) {
                const int r = cidx >> 3;
                const int c8 = cidx & 7;
                src = A + (size_t)(row0 + r) * 512 + kbase + c8 * 8;
                dst = smem_u32(st + r * TSTR + c8 * 8);
            } else {
                const int rem = cidx - 2048;
                const int r = rem >> 3;
                const int c8 = rem & 7;
                src = Bw + (size_t)(col0 + r) * 512 + kbase + c8 * 8;
                dst = smem_u32(st + TILE_A_E + r * TSTR + c8 * 8);
            }
            asm volatile("cp.async.cg.shared.global [%0], [%1], 16;"
                         :: "r"(dst), "l"(src));
        }
        asm volatile("cp.async.commit_group;");
    };

    float acc[4][8][4];
#pragma unroll
    for (int im = 0; im < 4; im++)
#pragma unroll
        for (int in_ = 0; in_ < 8; in_++)
#pragma unroll
            for (int e = 0; e < 4; e++) acc[im][in_][e] = 0.f;

    issue(0, 0);
    for (int ko = 0; ko < 8; ko++) {
        const int buf = ko & 1;
        if (ko + 1 < 8) {
            issue(ko + 1, buf ^ 1);
            asm volatile("cp.async.wait_group 1;");
        } else {
            asm volatile("cp.async.wait_group 0;");
        }
        __syncthreads();

        const __half* Ap = smem + buf * STAGE_E;
        const __half* Bp = Ap + TILE_A_E;

#pragma unroll
        for (int ks = 0; ks < 4; ks++) {
            const int kofs = ks * 16;
            uint32_t af[4][4];
#pragma unroll
            for (int im = 0; im < 4; im++) {
                const int rb = wm * 64 + im * 16 + g;
                af[im][0] = *(const uint32_t*)(Ap + rb * TSTR + kofs + cq * 2);
                af[im][1] = *(const uint32_t*)(Ap + (rb + 8) * TSTR + kofs + cq * 2);
                af[im][2] = *(const uint32_t*)(Ap + rb * TSTR + kofs + 8 + cq * 2);
                af[im][3] = *(const uint32_t*)(Ap + (rb + 8) * TSTR + kofs + 8 + cq * 2);
            }
#pragma unroll
            for (int in_ = 0; in_ < 8; in_++) {
                const int nr = wn * 64 + in_ * 8 + g;
                const uint32_t b0 = *(const uint32_t*)(Bp + nr * TSTR + kofs + cq * 2);
                const uint32_t b1 = *(const uint32_t*)(Bp + nr * TSTR + kofs + 8 + cq * 2);
#pragma unroll
                for (int im = 0; im < 4; im++)
                    mma16816h(acc[im][in_], af[im], b0, b1);
            }
        }
        __syncthreads();
    }

    // Epilogue
#pragma unroll
    for (int im = 0; im < 4; im++) {
#pragma unroll
        for (int in_ = 0; in_ < 8; in_++) {
            const int C0 = col0 + wn * 64 + in_ * 8 + cq * 2;
#pragma unroll
            for (int half = 0; half < 2; half++) {
                const int R = row0 + wm * 64 + im * 16 + g + half * 8;
                float vx = acc[im][in_][half * 2];
                float vy = acc[im][in_][half * 2 + 1];
                if (mode == 0) {
                    const int b2 = R >> 12, n2 = R & 4095;
                    const int w = n2 >> 5, jw = n2 & 31;
                    const int part = C0 >> 9;
                    const int h = (C0 & 511) >> 6;
                    const int dh = C0 & 63;
                    const size_t idx = (((size_t)((b2 * HH + h) * PP + jw)) * WW + w) * DH + dh;
                    uint32_t hi, lo;
                    pack_split(vx, vy, hi, lo);
                    __nv_bfloat16* d0 = (part == 0 ? g_q0 : part == 1 ? g_k0 : g_v0);
                    __nv_bfloat16* d1 = (part == 0 ? g_q1 : part == 1 ? g_k1 : g_v1);
                    *(uint32_t*)(d0 + idx) = hi;
                    *(uint32_t*)(d1 + idx) = lo;
                } else {
                    const int b2 = R >> 12, n2 = R & 4095;
                    const int dstn = (n2 + DISP) & 4095;
                    float2 v2;
                    v2.x = vx + __ldg(&bias[C0]);
                    v2.y = vy + __ldg(&bias[C0 + 1]);
                    *(float2*)(Out + (size_t)(b2 * NTOK + dstn) * DMODEL + C0) = v2;
                }
            }
        }
    }
}

// ---------------------------------------------------------------------------
// K2: tensor-core window attention (mask-split into two 64-key halves),
// bf16 3-pass. Epilogue emits single fp16 AO for K3.
// ---------------------------------------------------------------------------
#define ATSTR 72
#define ATILE_E (WW*ATSTR)
#define ATILE_B (ATILE_E*2)
#define ATT_SMEM (1024 + 6*ATILE_B)          // 111616 B

__global__ __launch_bounds__(256) void attn_kernel(const float* __restrict__ pos_emb) {
    extern __shared__ char smem_raw[];
    float* slut = (float*)smem_raw;
    __nv_bfloat16* tiles = (__nv_bfloat16*)(smem_raw + 1024);

    const int bid = blockIdx.x;
    const int tid = threadIdx.x;
    const int wid = tid >> 5;
    const int lid = tid & 31;
    const int g = lid >> 2, cq = lid & 3;

    if (tid < 2 * WW - 1) slut[tid] = pos_emb[tid];

    const size_t woff = (size_t)bid * (WW * DH);
    const __nv_bfloat16* srcs[6] = { g_q0 + woff, g_q1 + woff, g_k0 + woff,
                                     g_k1 + woff, g_v0 + woff, g_v1 + woff };
#pragma unroll
    for (int arr = 0; arr < 6; arr++) {
        const __nv_bfloat16* src = srcs[arr];
        __nv_bfloat16* tb = tiles + arr * ATILE_E;
#pragma unroll
        for (int ii = 0; ii < 4; ii++) {
            const int idx = ii * 256 + tid;
            const int r = idx >> 3, c8 = idx & 7;
            const uint32_t dst = smem_u32(tb + r * ATSTR + c8 * 8);
            asm volatile("cp.async.cg.shared.global [%0], [%1], 16;"
                         :: "r"(dst), "l"(src + r * 64 + c8 * 8));
        }
    }
    asm volatile("cp.async.commit_group;");
    asm volatile("cp.async.wait_group 0;");
    __syncthreads();

    const __nv_bfloat16* sq0 = tiles;
    const __nv_bfloat16* sq1 = tiles + ATILE_E;
    const __nv_bfloat16* sk0 = tiles + 2 * ATILE_E;
    const __nv_bfloat16* sk1 = tiles + 3 * ATILE_E;
    const __nv_bfloat16* sv0 = tiles + 4 * ATILE_E;
    const __nv_bfloat16* sv1 = tiles + 5 * ATILE_E;

    const int half = wid >> 2;
    const int mrow = (wid & 3) * 16;
    const int qrow0 = half * 64 + mrow;
    const int kbase = half * 64;

    float S[8][4];
#pragma unroll
    for (int nt = 0; nt < 8; nt++)
#pragma unroll
        for (int e = 0; e < 4; e++) S[nt][e] = 0.f;

#pragma unroll
    for (int ks = 0; ks < 4; ks++) {
        const int k0 = ks * 16;
        uint32_t aq0[4], aq1[4];
        aq0[0] = *(const uint32_t*)(sq0 + (qrow0 + g) * ATSTR + k0 + cq * 2);
        aq0[1] = *(const uint32_t*)(sq0 + (qrow0 + g + 8) * ATSTR + k0 + cq * 2);
        aq0[2] = *(const uint32_t*)(sq0 + (qrow0 + g) * ATSTR + k0 + 8 + cq * 2);
        aq0[3] = *(const uint32_t*)(sq0 + (qrow0 + g + 8) * ATSTR + k0 + 8 + cq * 2);
        aq1[0] = *(const uint32_t*)(sq1 + (qrow0 + g) * ATSTR + k0 + cq * 2);
        aq1[1] = *(const uint32_t*)(sq1 + (qrow0 + g + 8) * ATSTR + k0 + cq * 2);
        aq1[2] = *(const uint32_t*)(sq1 + (qrow0 + g) * ATSTR + k0 + 8 + cq * 2);
        aq1[3] = *(const uint32_t*)(sq1 + (qrow0 + g + 8) * ATSTR + k0 + 8 + cq * 2);
#pragma unroll
        for (int nt = 0; nt < 8; nt++) {
            const int krow = kbase + nt * 8 + g;
            const uint32_t b00 = *(const uint32_t*)(sk0 + krow * ATSTR + k0 + cq * 2);
            const uint32_t b01 = *(const uint32_t*)(sk0 + krow * ATSTR + k0 + 8 + cq * 2);
            const uint32_t b10 = *(const uint32_t*)(sk1 + krow * ATSTR + k0 + cq * 2);
            const uint32_t b11 = *(const uint32_t*)(sk1 + krow * ATSTR + k0 + 8 + cq * 2);
            mma16816(S[nt], aq0, b00, b01);
            mma16816(S[nt], aq0, b10, b11);
            mma16816(S[nt], aq1, b00, b01);
        }
    }

    const float scale = 0.125f;
    const int il0 = mrow + g;
    const int il1 = il0 + 8;
    float rs0 = 0.f, rs1 = 0.f;
#pragma unroll
    for (int nt = 0; nt < 8; nt++) {
        const int jl = nt * 8 + cq * 2;
        float p0 = __expf(S[nt][0] * scale + slut[jl - il0 + (WW - 1)]);
        float p1 = __expf(S[nt][1] * scale + slut[jl + 1 - il0 + (WW - 1)]);
        float p2 = __expf(S[nt][2] * scale + slut[jl - il1 + (WW - 1)]);
        float p3 = __expf(S[nt][3] * scale + slut[jl + 1 - il1 + (WW - 1)]);
        S[nt][0] = p0; S[nt][1] = p1; S[nt][2] = p2; S[nt][3] = p3;
        rs0 += p0 + p1;
        rs1 += p2 + p3;
    }
    rs0 += __shfl_xor_sync(0xFFFFFFFF, rs0, 1);
    rs0 += __shfl_xor_sync(0xFFFFFFFF, rs0, 2);
    rs1 += __shfl_xor_sync(0xFFFFFFFF, rs1, 1);
    rs1 += __shfl_xor_sync(0xFFFFFFFF, rs1, 2);
    const float inv0 = 1.0f / rs0;
    const float inv1 = 1.0f / rs1;

    uint32_t p0f[4][4], p1f[4][4];
#pragma unroll
    for (int ks = 0; ks < 4; ks++) {
        pack_split(S[2 * ks][0],     S[2 * ks][1],     p0f[ks][0], p1f[ks][0]);
        pack_split(S[2 * ks][2],     S[2 * ks][3],     p0f[ks][1], p1f[ks][1]);
        pack_split(S[2 * ks + 1][0], S[2 * ks + 1][1], p0f[ks][2], p1f[ks][2]);
        pack_split(S[2 * ks + 1][2], S[2 * ks + 1][3], p0f[ks][3], p1f[ks][3]);
    }

    float O[8][4];
#pragma unroll
    for (int nt = 0; nt < 8; nt++)
#pragma unroll
        for (int e = 0; e < 4; e++) O[nt][e] = 0.f;

#pragma unroll
    for (int ks = 0; ks < 4; ks++) {
        const int vrow = kbase + ks * 16 + (lid & 15);
#pragma unroll
        for (int nt = 0; nt < 8; nt++) {
            uint32_t vb00, vb01, vb10, vb11;
            ldsm_x2_trans(vb00, vb01, smem_u32(sv0 + vrow * ATSTR + nt * 8));
            ldsm_x2_trans(vb10, vb11, smem_u32(sv1 + vrow * ATSTR + nt * 8));
            mma16816(O[nt], p0f[ks], vb00, vb01);
            mma16816(O[nt], p0f[ks], vb10, vb11);
            mma16816(O[nt], p1f[ks], vb00, vb01);
        }
    }

    const int b  = bid >> 8;
    const int h  = (bid >> 5) & 7;
    const int jw = bid & 31;
    const int iw0 = half * 64 + il0;
    const int iw1 = half * 64 + il1;
    const size_t row0off = ((size_t)(b * NTOK + jw * WW + iw0)) * DMODEL + h * DH;
    const size_t row1off = ((size_t)(b * NTOK + jw * WW + iw1)) * DMODEL + h * DH;
#pragma unroll
    for (int nt = 0; nt < 8; nt++) {
        const int c = nt * 8 + cq * 2;
        *(uint32_t*)(g_ao + row0off + c) = pack_h2(O[nt][0] * inv0, O[nt][1] * inv0);
        *(uint32_t*)(g_ao + row1off + c) = pack_h2(O[nt][2] * inv1, O[nt][3] * inv1);
    }
}

// ---------------------------------------------------------------------------
extern "C" void kernel_launch(void* const* d_in, const int* in_sizes, int n_in,
                              void* d_out, int out_size) {
    const float* x       = (const float*)d_in[0];
    const float* Wqkv    = (const float*)d_in[1];
    const float* pos_emb = (const float*)d_in[2];
    const float* Wout    = (const float*)d_in[3];
    const float* bout    = (const float*)d_in[4];
    float* out = (float*)d_out;

    cudaFuncSetAttribute(gemm256, cudaFuncAttributeMaxDynamicSharedMemorySize, GEMM_SMEM);
    cudaFuncSetAttribute(attn_kernel, cudaFuncAttributeMaxDynamicSharedMemorySize, ATT_SMEM);

    conv_x_kernel<<<(BB * NTOK * DMODEL + 255) / 256, 256>>>(x);
    conv_w_kernel<<<(1536 * 512 + 255) / 256, 256>>>(Wqkv, 1536, 0);
    conv_w_kernel<<<(512 * 512 + 255) / 256, 256>>>(Wout, 512, 1);

    // K1: QKV (M=32768 -> 128 row blocks, N=1536 -> 12 col blocks)
    gemm256<<<dim3(12, 128), 256, GEMM_SMEM>>>(nullptr, nullptr, 0);
    // K2: attention, one window per block
    attn_kernel<<<2048, 256, ATT_SMEM>>>(pos_emb);
    // K3: output projection (N=512 -> 4 col blocks) + bias + roll
    gemm256<<<dim3(4, 128), 256, GEMM_SMEM>>>(bout, out, 1);
}